// round 11
// baseline (speedup 1.0000x reference)
#include <cuda_runtime.h>
#include <cuda_fp16.h>
#include <math.h>

#define Nn 50000
#define Ee 800000
#define ELn 100000
#define TOTE (Ee + Nn)
#define NTY 311

// ---------------- scratch (static device globals; no runtime alloc) -------------
__device__ __align__(16) __half g_feat16[Nn * 64];
__device__ __align__(16) __half g_h16[Nn * 256];
__device__ __align__(16) __half g_za16[Nn * 256];
__device__ __align__(16) __half g_zb16[Nn * 256];
__device__ __align__(16) __half g_w1t[256 * 64];
__device__ __align__(16) __half g_w2t[256 * 256];
__device__ __align__(16) __half g_w3t[128 * 256];
__device__ __align__(16) __half g_wl1t[64 * 256];
__device__ __align__(16) float  g_als[Nn * 4];
__device__ __align__(16) float  g_ald[Nn * 4];
__device__ int    g_deg[Nn];            // zero-init at load; scan re-zeroes each call
__device__ int    g_pos[Nn];
__device__ int    g_rowptr[Nn + 1];
__device__ __align__(16) int g_esrc[TOTE];

// ---------------- mma m16n8k16 fp16 -> fp32 -----------------------------------
__device__ __forceinline__ void mma16816(float* c, const unsigned* a, const unsigned* b) {
    asm volatile(
        "mma.sync.aligned.m16n8k16.row.col.f32.f16.f16.f32 "
        "{%0,%1,%2,%3}, {%4,%5,%6,%7}, {%8,%9}, {%0,%1,%2,%3};"
        : "+f"(c[0]), "+f"(c[1]), "+f"(c[2]), "+f"(c[3])
        : "r"(a[0]), "r"(a[1]), "r"(a[2]), "r"(a[3]), "r"(b[0]), "r"(b[1]));
}

// ---------------- prep A: degree count (graph branch) --------------------------
__global__ void k_prep_graph(const int* __restrict__ ei) {
    int idx = blockIdx.x * blockDim.x + threadIdx.x;
    if (idx < Ee) atomicAdd(&g_deg[ei[Ee + idx]], 1);
}

// ---------------- prep B: feat16 + weight cvt/transpose (data branch) ----------
#define PREPD_TASKS (Nn * 64 + 256 * 64 + 256 * 256 + 128 * 256 + 64 * 256)
__global__ void k_prep_data(const float* __restrict__ x, const float* __restrict__ emb,
                            const float* __restrict__ W1, const float* __restrict__ W2,
                            const float* __restrict__ W3, const float* __restrict__ Wl1) {
    int t2 = blockIdx.x * blockDim.x + threadIdx.x;
    if (t2 >= PREPD_TASKS) return;
    if (t2 < Nn * 64) {
        int n = t2 >> 6, c = t2 & 63;
        float v;
        if (c < 16) {
            int ty = (int)x[(size_t)n * 33];
            v = emb[ty * 16 + c];
        } else if (c < 48)
            v = x[(size_t)n * 33 + 1 + (c - 16)];
        else
            v = 0.f;
        g_feat16[t2] = __float2half_rn(v);
        return;
    }
    int t3 = t2 - Nn * 64;
    if (t3 < 256 * 64) {
        int n = t3 >> 6, k = t3 & 63;
        g_w1t[t3] = __float2half_rn(k < 48 ? W1[k * 256 + n] : 0.f);
        return;
    }
    t3 -= 256 * 64;
    if (t3 < 256 * 256) {
        int n = t3 >> 8, k = t3 & 255;
        g_w2t[t3] = __float2half_rn(W2[k * 256 + n]);
        return;
    }
    t3 -= 256 * 256;
    if (t3 < 128 * 256) {
        int n = t3 >> 8, k = t3 & 255;
        g_w3t[t3] = __float2half_rn(W3[k * 128 + n]);
        return;
    }
    t3 -= 128 * 256;
    {
        int n = t3 >> 8, k = t3 & 255;
        g_wl1t[t3] = __float2half_rn(Wl1[k * 64 + n]);
    }
}

// ---------------- scan (adds +1 self loop, re-zeroes deg for next replay) ------
__global__ void k_scan() {
    __shared__ int sh[1024];
    const int CH = (Nn + 1023) / 1024;
    int t = threadIdx.x;
    int base = t * CH;
    int s = 0;
    for (int i = 0; i < CH; i++) {
        int idx = base + i;
        if (idx < Nn) s += g_deg[idx] + 1;
    }
    sh[t] = s;
    __syncthreads();
    for (int off = 1; off < 1024; off <<= 1) {
        int v = (t >= off) ? sh[t - off] : 0;
        __syncthreads();
        sh[t] += v;
        __syncthreads();
    }
    int run = (t == 0) ? 0 : sh[t - 1];
    for (int i = 0; i < CH; i++) {
        int idx = base + i;
        if (idx < Nn) {
            int d = g_deg[idx] + 1;
            g_deg[idx] = 0;
            g_rowptr[idx] = run;
            g_pos[idx] = run;
            run += d;
        }
    }
    if (t == 1023) g_rowptr[Nn] = run;
}

__global__ void k_fill(const int* __restrict__ ei) {
    int t = blockIdx.x * blockDim.x + threadIdx.x;
    if (t < Ee) {
        int s = ei[t], d = ei[Ee + t];
        int p = atomicAdd(&g_pos[d], 1);
        g_esrc[p] = s;
    } else if (t < TOTE) {
        int n = t - Ee;
        int p = atomicAdd(&g_pos[n], 1);
        g_esrc[p] = n;
    }
}

// ---------------- fp16 tensor-core GEMM: C16[M,N] = A[M,K] @ Bt[N,K]^T ---------
__global__ __launch_bounds__(256) void k_gemm_h(const __half* __restrict__ A,
                                                const __half* __restrict__ Bt,
                                                __half* __restrict__ C16, int M_,
                                                int K, int N) {
    __shared__ __align__(16) __half As[2][128][40];
    __shared__ __align__(16) __half Bs[2][128][40];
    int tid = threadIdx.x;
    int brow = blockIdx.y * 128, bcol = blockIdx.x * 128;
    int w = tid >> 5, lane = tid & 31;
    int wm = w & 1, wn = w >> 1;
    int g = lane >> 2, t4 = lane & 3;

    float acc[4][4][4];
#pragma unroll
    for (int mt = 0; mt < 4; mt++)
#pragma unroll
        for (int nt = 0; nt < 4; nt++)
#pragma unroll
            for (int p = 0; p < 4; p++) acc[mt][nt][p] = 0.f;

    int lr = tid >> 1;
    int lc = (tid & 1) * 16;
    uint4 aR[2], bR[2];

    auto LOAD = [&](int kt) {
        int arow = brow + lr;
        if (arow < M_) {
            const __half* ap = A + (size_t)arow * K + kt * 32 + lc;
            aR[0] = *(const uint4*)ap;
            aR[1] = *(const uint4*)(ap + 8);
        } else {
            aR[0] = make_uint4(0, 0, 0, 0);
            aR[1] = make_uint4(0, 0, 0, 0);
        }
        const __half* bp = Bt + (size_t)(bcol + lr) * K + kt * 32 + lc;
        bR[0] = *(const uint4*)bp;
        bR[1] = *(const uint4*)(bp + 8);
    };
    auto STS = [&](int bf) {
        *(uint4*)&As[bf][lr][lc] = aR[0];
        *(uint4*)&As[bf][lr][lc + 8] = aR[1];
        *(uint4*)&Bs[bf][lr][lc] = bR[0];
        *(uint4*)&Bs[bf][lr][lc + 8] = bR[1];
    };

    int KT = K >> 5;
    LOAD(0);
    STS(0);
    __syncthreads();

    for (int kt = 0; kt < KT; kt++) {
        int bf = kt & 1;
        if (kt + 1 < KT) LOAD(kt + 1);
#pragma unroll
        for (int ks = 0; ks < 2; ks++) {
            int kb = ks * 16 + 2 * t4;
            unsigned af[4][4], bfr[4][2];
#pragma unroll
            for (int mt = 0; mt < 4; mt++) {
                int r0 = wm * 64 + mt * 16 + g;
                af[mt][0] = *(const unsigned*)&As[bf][r0][kb];
                af[mt][1] = *(const unsigned*)&As[bf][r0 + 8][kb];
                af[mt][2] = *(const unsigned*)&As[bf][r0][kb + 8];
                af[mt][3] = *(const unsigned*)&As[bf][r0 + 8][kb + 8];
            }
#pragma unroll
            for (int nt = 0; nt < 4; nt++) {
                int n0 = wn * 32 + nt * 8 + g;
                bfr[nt][0] = *(const unsigned*)&Bs[bf][n0][kb];
                bfr[nt][1] = *(const unsigned*)&Bs[bf][n0][kb + 8];
            }
#pragma unroll
            for (int mt = 0; mt < 4; mt++)
#pragma unroll
                for (int nt = 0; nt < 4; nt++) mma16816(acc[mt][nt], af[mt], bfr[nt]);
        }
        if (kt + 1 < KT) {
            STS(bf ^ 1);
            __syncthreads();
        }
    }

#pragma unroll
    for (int mt = 0; mt < 4; mt++) {
        int r0 = brow + wm * 64 + mt * 16 + g;
#pragma unroll
        for (int nt = 0; nt < 4; nt++) {
            int c0 = bcol + wn * 32 + nt * 8 + 2 * t4;
            if (r0 < M_)
                *(__half2*)(C16 + (size_t)r0 * N + c0) =
                    __floats2half2_rn(acc[mt][nt][0], acc[mt][nt][1]);
            if (r0 + 8 < M_)
                *(__half2*)(C16 + (size_t)(r0 + 8) * N + c0) =
                    __floats2half2_rn(acc[mt][nt][2], acc[mt][nt][3]);
        }
    }
}

// ---------------- per-node attention coefficients (fp16 h) --------------------
__global__ void k_coef(const __half* __restrict__ hbuf, const float* __restrict__ asrc,
                       const float* __restrict__ adst, int H, int D) {
    int idx = blockIdx.x * blockDim.x + threadIdx.x;
    if (idx >= Nn * H) return;
    int n = idx / H, h = idx % H;
    const uint4* hp = (const uint4*)(hbuf + (size_t)n * H * D + h * D);
    const float4* as = (const float4*)(asrc + h * D);
    const float4* ad = (const float4*)(adst + h * D);
    float ss = 0.f, sd = 0.f;
    for (int j = 0; j < D / 8; j++) {
        uint4 hv = hp[j];
        float2 p0 = __half22float2(*(__half2*)&hv.x);
        float2 p1 = __half22float2(*(__half2*)&hv.y);
        float2 p2 = __half22float2(*(__half2*)&hv.z);
        float2 p3 = __half22float2(*(__half2*)&hv.w);
        float4 a0 = as[2 * j], a1 = as[2 * j + 1];
        float4 d0 = ad[2 * j], d1 = ad[2 * j + 1];
        ss += p0.x * a0.x + p0.y * a0.y + p1.x * a0.z + p1.y * a0.w + p2.x * a1.x +
              p2.y * a1.y + p3.x * a1.z + p3.y * a1.w;
        sd += p0.x * d0.x + p0.y * d0.y + p1.x * d0.z + p1.y * d0.w + p2.x * d1.x +
              p2.y * d1.y + p3.x * d1.z + p3.y * d1.w;
    }
    g_als[idx] = ss;
    g_ald[idx] = sd;
}

// ---------------- aggregation: 2 warps per node, 4-edge unroll + prefetch ------
// Even/odd 4-edge groups go to warp-half 0/1 of the pair; lane-wise partial
// (acc, den) combined through smem. Nn % 4 == 0 so no divergent-exit barrier.
template <int H, int D, int ACT>
__global__ __launch_bounds__(256) void k_aggr(const __half* __restrict__ h16,
                                              const float* __restrict__ bias,
                                              __half* __restrict__ outh) {
    constexpr int HD = H * D;
    constexpr int F = HD / 32;  // 8 or 4
    __shared__ float sred[4][32][F + 1];

    int tid = threadIdx.x;
    int pair = tid >> 6;        // 4 nodes per block
    int w2 = (tid >> 5) & 1;    // warp-half within pair
    int lane = tid & 31;
    int n = blockIdx.x * 4 + pair;  // grid sized so n < Nn always
    int beg = g_rowptr[n], end = g_rowptr[n + 1];
    const int fb = lane * F;
    const int myh = fb / D;
    const float am = g_ald[n * H + myh];

    float den = 0.f;
    float acc[F];
#pragma unroll
    for (int j = 0; j < F; j++) acc[j] = 0.f;

    auto GATHER = [&](int s, float* hf) {
        if constexpr (F == 8) {
            uint4 hv = *(const uint4*)(h16 + (size_t)s * HD + fb);
            float2 p0 = __half22float2(*(__half2*)&hv.x);
            float2 p1 = __half22float2(*(__half2*)&hv.y);
            float2 p2 = __half22float2(*(__half2*)&hv.z);
            float2 p3 = __half22float2(*(__half2*)&hv.w);
            hf[0] = p0.x; hf[1] = p0.y; hf[2] = p1.x; hf[3] = p1.y;
            hf[4] = p2.x; hf[5] = p2.y; hf[6] = p3.x; hf[7] = p3.y;
        } else {
            uint2 hv = *(const uint2*)(h16 + (size_t)s * HD + fb);
            float2 p0 = __half22float2(*(__half2*)&hv.x);
            float2 p1 = __half22float2(*(__half2*)&hv.y);
            hf[0] = p0.x; hf[1] = p0.y; hf[2] = p1.x; hf[3] = p1.y;
        }
    };
    auto ONE = [&](int s0) {
        float l0 = g_als[s0 * H + myh] + am;
        l0 = l0 > 0.f ? l0 : 0.2f * l0;
        float ha[F];
        GATHER(s0, ha);
        float w0 = __expf(l0);
        den += w0;
#pragma unroll
        for (int j = 0; j < F; j++) acc[j] = fmaf(w0, ha[j], acc[j]);
    };

    int aligned = (beg + 3) & ~3;
    if (aligned > end) aligned = end;
    if (w2 == 0)  // warp-half 0 peels the unaligned head
        for (int i = beg; i < aligned; i++) ONE(g_esrc[i]);

    int base = aligned;
    int G = (end - base) >> 2;
    int g = w2;
    if (g < G) {
        int4 s4 = *(const int4*)(g_esrc + base + 4 * g);
        for (; g < G; g += 2) {
            int4 s4n = (g + 2 < G) ? *(const int4*)(g_esrc + base + 4 * (g + 2)) : s4;
            float l0 = g_als[s4.x * H + myh] + am;
            float l1 = g_als[s4.y * H + myh] + am;
            float l2 = g_als[s4.z * H + myh] + am;
            float l3 = g_als[s4.w * H + myh] + am;
            float ha[F], hb[F], hc[F], hd[F];
            GATHER(s4.x, ha);
            GATHER(s4.y, hb);
            GATHER(s4.z, hc);
            GATHER(s4.w, hd);
            l0 = l0 > 0.f ? l0 : 0.2f * l0;
            l1 = l1 > 0.f ? l1 : 0.2f * l1;
            l2 = l2 > 0.f ? l2 : 0.2f * l2;
            l3 = l3 > 0.f ? l3 : 0.2f * l3;
            float w0 = __expf(l0), w1 = __expf(l1);
            float w2e = __expf(l2), w3 = __expf(l3);
            den += (w0 + w1) + (w2e + w3);
#pragma unroll
            for (int j = 0; j < F; j++) {
                float t0 = fmaf(w0, ha[j], w1 * hb[j]);
                float t1 = fmaf(w2e, hc[j], w3 * hd[j]);
                acc[j] += t0 + t1;
            }
            s4 = s4n;
        }
    }
    if (w2 == 1)  // warp-half 1 takes the tail
        for (int i = base + 4 * G; i < end; i++) ONE(g_esrc[i]);

    // pair combine (lane-wise)
    if (w2 == 1) {
#pragma unroll
        for (int j = 0; j < F; j++) sred[pair][lane][j] = acc[j];
        sred[pair][lane][F] = den;
    }
    __syncthreads();
    if (w2 == 0) {
#pragma unroll
        for (int j = 0; j < F; j++) acc[j] += sred[pair][lane][j];
        den += sred[pair][lane][F];

        float inv = 1.f / (den + 1e-16f);
        float o[F];
#pragma unroll
        for (int j = 0; j < F; j++) {
            float v = acc[j] * inv + bias[fb + j];
            if (ACT) v = v > 0.f ? v : (__expf(v) - 1.f);
            o[j] = v;
        }
        if constexpr (F == 8) {
            __half2 q0 = __floats2half2_rn(o[0], o[1]);
            __half2 q1 = __floats2half2_rn(o[2], o[3]);
            __half2 q2 = __floats2half2_rn(o[4], o[5]);
            __half2 q3 = __floats2half2_rn(o[6], o[7]);
            uint4 hv;
            hv.x = *(unsigned*)&q0;
            hv.y = *(unsigned*)&q1;
            hv.z = *(unsigned*)&q2;
            hv.w = *(unsigned*)&q3;
            *(uint4*)(outh + (size_t)n * HD + fb) = hv;
        } else {
            __half2 q0 = __floats2half2_rn(o[0], o[1]);
            __half2 q1 = __floats2half2_rn(o[2], o[3]);
            uint2 hv;
            hv.x = *(unsigned*)&q0;
            hv.y = *(unsigned*)&q1;
            *(uint2*)(outh + (size_t)n * HD + fb) = hv;
        }
    }
}

// ---------------- decoder: tensor-core GEMM, 256 edges x 64 outs per block -----
#define DEC_M 256
__global__ __launch_bounds__(256) void k_decode3(const __half* __restrict__ z16,
                                                 const int* __restrict__ eli,
                                                 const float* __restrict__ x,
                                                 const __half* __restrict__ Wl1t,
                                                 const float* __restrict__ bl1,
                                                 const float* __restrict__ Wl2,
                                                 const float* __restrict__ bl2,
                                                 const float* __restrict__ tb,
                                                 float* __restrict__ out) {
    extern __shared__ __align__(16) __half ds[];
    __half* Asm = ds;                    // [256][264]
    __half* Wsm = ds + 256 * 264;        // [64][264]
    int* sls = (int*)(Wsm + 64 * 264);
    int* sld = sls + DEC_M;

    int tid = threadIdx.x;
    int e0 = blockIdx.x * DEC_M;

    for (int i = tid; i < DEC_M; i += 256) {
        int e = e0 + i;
        sls[i] = (e < ELn) ? eli[e] : 0;
        sld[i] = (e < ELn) ? eli[ELn + e] : 0;
    }
    for (int i = tid; i < 64 * 32; i += 256) {
        int nr = i >> 5, kc = (i & 31) * 8;
        *(uint4*)&Wsm[nr * 264 + kc] = *(const uint4*)&Wl1t[nr * 256 + kc];
    }
    __syncthreads();

    for (int i = tid; i < DEC_M * 32; i += 256) {
        int e = i >> 5, off = i & 31;
        int node = (off < 16) ? sls[e] : sld[e];
        int kc = (off & 15) * 8;
        *(uint4*)&Asm[e * 264 + (off < 16 ? 0 : 128) + kc] =
            *(const uint4*)&z16[(size_t)node * 128 + kc];
    }
    __syncthreads();

    int w = tid >> 5, lane = tid & 31;
    int g = lane >> 2, t4 = lane & 3;

    float acc[2][8][4];
#pragma unroll
    for (int mt = 0; mt < 2; mt++)
#pragma unroll
        for (int nt = 0; nt < 8; nt++)
#pragma unroll
            for (int p = 0; p < 4; p++) acc[mt][nt][p] = 0.f;

#pragma unroll 4
    for (int ks = 0; ks < 16; ks++) {
        int kb = ks * 16 + 2 * t4;
        unsigned af[2][4];
#pragma unroll
        for (int mt = 0; mt < 2; mt++) {
            int r0 = w * 32 + mt * 16 + g;
            af[mt][0] = *(const unsigned*)&Asm[r0 * 264 + kb];
            af[mt][1] = *(const unsigned*)&Asm[(r0 + 8) * 264 + kb];
            af[mt][2] = *(const unsigned*)&Asm[r0 * 264 + kb + 8];
            af[mt][3] = *(const unsigned*)&Asm[(r0 + 8) * 264 + kb + 8];
        }
#pragma unroll
        for (int nt = 0; nt < 8; nt++) {
            int n0 = nt * 8 + g;
            unsigned bfr[2];
            bfr[0] = *(const unsigned*)&Wsm[n0 * 264 + kb];
            bfr[1] = *(const unsigned*)&Wsm[n0 * 264 + kb + 8];
            mma16816(acc[0][nt], af[0], bfr);
            mma16816(acc[1][nt], af[1], bfr);
        }
    }

    float b1v[16], w2v[16];
#pragma unroll
    for (int nt = 0; nt < 8; nt++) {
        int c0 = nt * 8 + 2 * t4;
        b1v[2 * nt] = bl1[c0];
        b1v[2 * nt + 1] = bl1[c0 + 1];
        w2v[2 * nt] = Wl2[c0];
        w2v[2 * nt + 1] = Wl2[c0 + 1];
    }
    float b2 = bl2[0];

#pragma unroll
    for (int mt = 0; mt < 2; mt++) {
        float p0 = 0.f, p1 = 0.f;
#pragma unroll
        for (int nt = 0; nt < 8; nt++) {
            float h00 = fmaxf(acc[mt][nt][0] + b1v[2 * nt], 0.f);
            float h01 = fmaxf(acc[mt][nt][1] + b1v[2 * nt + 1], 0.f);
            p0 = fmaf(h00, w2v[2 * nt], p0);
            p0 = fmaf(h01, w2v[2 * nt + 1], p0);
            float h10 = fmaxf(acc[mt][nt][2] + b1v[2 * nt], 0.f);
            float h11 = fmaxf(acc[mt][nt][3] + b1v[2 * nt + 1], 0.f);
            p1 = fmaf(h10, w2v[2 * nt], p1);
            p1 = fmaf(h11, w2v[2 * nt + 1], p1);
        }
        p0 += __shfl_xor_sync(0xffffffffu, p0, 1);
        p0 += __shfl_xor_sync(0xffffffffu, p0, 2);
        p1 += __shfl_xor_sync(0xffffffffu, p1, 1);
        p1 += __shfl_xor_sync(0xffffffffu, p1, 2);
        if (t4 == 0) {
            int r = w * 32 + mt * 16 + g;
            int e = e0 + r;
            if (e < ELn) {
                int tls = (int)x[(size_t)sls[r] * 33];
                int tld = (int)x[(size_t)sld[r] * 33];
                out[e] = p0 + b2 + tb[tls * NTY + tld];
            }
            e = e0 + r + 8;
            if (e < ELn) {
                int tls = (int)x[(size_t)sls[r + 8] * 33];
                int tld = (int)x[(size_t)sld[r + 8] * 33];
                out[e] = p1 + b2 + tb[tls * NTY + tld];
            }
        }
    }
}

// ---------------- launch -------------
extern "C" void kernel_launch(void* const* d_in, const int* in_sizes, int n_in,
                              void* d_out, int out_size) {
    const float* x = (const float*)d_in[0];
    const int* ei = (const int*)d_in[1];
    const int* eli = (const int*)d_in[2];
    const float* emb = (const float*)d_in[3];
    const float* W1 = (const float*)d_in[4];
    const float* as1 = (const float*)d_in[5];
    const float* ad1 = (const float*)d_in[6];
    const float* b1 = (const float*)d_in[7];
    const float* W2 = (const float*)d_in[8];
    const float* as2 = (const float*)d_in[9];
    const float* ad2 = (const float*)d_in[10];
    const float* b2 = (const float*)d_in[11];
    const float* W3 = (const float*)d_in[12];
    const float* as3 = (const float*)d_in[13];
    const float* ad3 = (const float*)d_in[14];
    const float* b3 = (const float*)d_in[15];
    const float* Wl1 = (const float*)d_in[16];
    const float* bl1 = (const float*)d_in[17];
    const float* Wl2 = (const float*)d_in[18];
    const float* bl2 = (const float*)d_in[19];
    const float* tb = (const float*)d_in[20];
    float* out = (float*)d_out;

    __half *feat16, *h16, *za16, *zb16, *w1t, *w2t, *w3t, *wl1t;
    cudaGetSymbolAddress((void**)&feat16, g_feat16);
    cudaGetSymbolAddress((void**)&h16, g_h16);
    cudaGetSymbolAddress((void**)&za16, g_za16);
    cudaGetSymbolAddress((void**)&zb16, g_zb16);
    cudaGetSymbolAddress((void**)&w1t, g_w1t);
    cudaGetSymbolAddress((void**)&w2t, g_w2t);
    cudaGetSymbolAddress((void**)&w3t, g_w3t);
    cudaGetSymbolAddress((void**)&wl1t, g_wl1t);

    const int AGB = Nn / 4;  // 12500 blocks, 4 nodes (2 warps each) per block
    const int GY = (Nn + 127) / 128;

    // Fork-join: CSR build runs concurrently with data prep + layer-1 GEMM + coef.
    cudaStream_t sb = 0;
    cudaEvent_t evFork = nullptr, evJoin = nullptr;
    bool forked = (cudaStreamCreateWithFlags(&sb, cudaStreamNonBlocking) == cudaSuccess) &&
                  (cudaEventCreateWithFlags(&evFork, cudaEventDisableTiming) == cudaSuccess) &&
                  (cudaEventCreateWithFlags(&evJoin, cudaEventDisableTiming) == cudaSuccess);

    if (forked) {
        cudaEventRecord(evFork, 0);
        cudaStreamWaitEvent(sb, evFork, 0);
        k_prep_graph<<<(Ee + 255) / 256, 256, 0, sb>>>(ei);
        k_scan<<<1, 1024, 0, sb>>>();
        k_fill<<<(TOTE + 255) / 256, 256, 0, sb>>>(ei);
        cudaEventRecord(evJoin, sb);
    } else {
        k_prep_graph<<<(Ee + 255) / 256, 256>>>(ei);
        k_scan<<<1, 1024>>>();
        k_fill<<<(TOTE + 255) / 256, 256>>>(ei);
    }

    // main stream: data prep + layer-1 GEMM + coef (independent of CSR)
    k_prep_data<<<(PREPD_TASKS + 255) / 256, 256>>>(x, emb, W1, W2, W3, Wl1);
    k_gemm_h<<<dim3(2, GY), 256>>>(feat16, w1t, h16, Nn, 64, 256);
    k_coef<<<(Nn * 4 + 255) / 256, 256>>>(h16, as1, ad1, 4, 64);

    if (forked) cudaStreamWaitEvent(0, evJoin, 0);

    // layer 1 aggregation (needs CSR + coef)
    k_aggr<4, 64, 1><<<AGB, 256>>>(h16, b1, za16);

    // layer 2
    k_gemm_h<<<dim3(2, GY), 256>>>(za16, w2t, h16, Nn, 256, 256);
    k_coef<<<(Nn * 2 + 255) / 256, 256>>>(h16, as2, ad2, 2, 128);
    k_aggr<2, 128, 1><<<AGB, 256>>>(h16, b2, zb16);

    // layer 3 (output fp16, 128 wide -> za16 reused)
    k_gemm_h<<<dim3(1, GY), 256>>>(zb16, w3t, h16, Nn, 256, 128);
    k_coef<<<(Nn * 1 + 255) / 256, 256>>>(h16, as3, ad3, 1, 128);
    k_aggr<1, 128, 0><<<AGB, 256>>>(h16, b3, za16);

    // decoder (tensor core)
    const int DSMEM = (256 * 264 + 64 * 264) * 2 + 2 * DEC_M * 4;  // ~171KB
    cudaFuncSetAttribute(k_decode3, cudaFuncAttributeMaxDynamicSharedMemorySize, DSMEM);
    k_decode3<<<(ELn + DEC_M - 1) / DEC_M, 256, DSMEM>>>(za16, eli, x, wl1t, bl1, Wl2, bl2,
                                                         tb, out);
}

// round 12
// speedup vs baseline: 1.1337x; 1.1337x over previous
#include <cuda_runtime.h>
#include <cuda_fp16.h>
#include <math.h>

#define Nn 50000
#define Ee 800000
#define ELn 100000
#define TOTE (Ee + Nn)
#define NTY 311

// ---------------- scratch (static device globals; no runtime alloc) -------------
__device__ __align__(16) __half g_feat16[Nn * 64];
__device__ __align__(16) __half g_h16[Nn * 256];
__device__ __align__(16) __half g_za16[Nn * 256];
__device__ __align__(16) __half g_zb16[Nn * 256];
__device__ __align__(16) __half g_w1t[256 * 64];
__device__ __align__(16) __half g_w2t[256 * 256];
__device__ __align__(16) __half g_w3t[128 * 256];
__device__ __align__(16) __half g_wl1t[64 * 256];
__device__ __align__(16) float  g_als[Nn * 4];
__device__ __align__(16) float  g_ald[Nn * 4];
__device__ int    g_deg[Nn];            // zero-init at load; scan re-zeroes each call
__device__ int    g_pos[Nn];
__device__ int    g_rowptr[Nn + 1];
__device__ __align__(16) int g_esrc[TOTE];

// ---------------- mma m16n8k16 fp16 -> fp32 -----------------------------------
__device__ __forceinline__ void mma16816(float* c, const unsigned* a, const unsigned* b) {
    asm volatile(
        "mma.sync.aligned.m16n8k16.row.col.f32.f16.f16.f32 "
        "{%0,%1,%2,%3}, {%4,%5,%6,%7}, {%8,%9}, {%0,%1,%2,%3};"
        : "+f"(c[0]), "+f"(c[1]), "+f"(c[2]), "+f"(c[3])
        : "r"(a[0]), "r"(a[1]), "r"(a[2]), "r"(a[3]), "r"(b[0]), "r"(b[1]));
}

// cp.async 16B with zero-fill when invalid (src-size 0)
__device__ __forceinline__ void cp16(unsigned dst, const void* src, bool v) {
    int sz = v ? 16 : 0;
    asm volatile("cp.async.cg.shared.global [%0], [%1], 16, %2;" ::"r"(dst), "l"(src),
                 "r"(sz));
}

// ---------------- prep A: degree count (graph branch) --------------------------
__global__ void k_prep_graph(const int* __restrict__ ei) {
    int idx = blockIdx.x * blockDim.x + threadIdx.x;
    if (idx < Ee) atomicAdd(&g_deg[ei[Ee + idx]], 1);
}

// ---------------- prep B: feat16 + weight cvt/transpose (data branch) ----------
#define PREPD_TASKS (Nn * 64 + 256 * 64 + 256 * 256 + 128 * 256 + 64 * 256)
__global__ void k_prep_data(const float* __restrict__ x, const float* __restrict__ emb,
                            const float* __restrict__ W1, const float* __restrict__ W2,
                            const float* __restrict__ W3, const float* __restrict__ Wl1) {
    int t2 = blockIdx.x * blockDim.x + threadIdx.x;
    if (t2 >= PREPD_TASKS) return;
    if (t2 < Nn * 64) {
        int n = t2 >> 6, c = t2 & 63;
        float v;
        if (c < 16) {
            int ty = (int)x[(size_t)n * 33];
            v = emb[ty * 16 + c];
        } else if (c < 48)
            v = x[(size_t)n * 33 + 1 + (c - 16)];
        else
            v = 0.f;
        g_feat16[t2] = __float2half_rn(v);
        return;
    }
    int t3 = t2 - Nn * 64;
    if (t3 < 256 * 64) {
        int n = t3 >> 6, k = t3 & 63;
        g_w1t[t3] = __float2half_rn(k < 48 ? W1[k * 256 + n] : 0.f);
        return;
    }
    t3 -= 256 * 64;
    if (t3 < 256 * 256) {
        int n = t3 >> 8, k = t3 & 255;
        g_w2t[t3] = __float2half_rn(W2[k * 256 + n]);
        return;
    }
    t3 -= 256 * 256;
    if (t3 < 128 * 256) {
        int n = t3 >> 8, k = t3 & 255;
        g_w3t[t3] = __float2half_rn(W3[k * 128 + n]);
        return;
    }
    t3 -= 128 * 256;
    {
        int n = t3 >> 8, k = t3 & 255;
        g_wl1t[t3] = __float2half_rn(Wl1[k * 64 + n]);
    }
}

// ---------------- scan (adds +1 self loop, re-zeroes deg for next replay) ------
__global__ void k_scan() {
    __shared__ int sh[1024];
    const int CH = (Nn + 1023) / 1024;
    int t = threadIdx.x;
    int base = t * CH;
    int s = 0;
    for (int i = 0; i < CH; i++) {
        int idx = base + i;
        if (idx < Nn) s += g_deg[idx] + 1;
    }
    sh[t] = s;
    __syncthreads();
    for (int off = 1; off < 1024; off <<= 1) {
        int v = (t >= off) ? sh[t - off] : 0;
        __syncthreads();
        sh[t] += v;
        __syncthreads();
    }
    int run = (t == 0) ? 0 : sh[t - 1];
    for (int i = 0; i < CH; i++) {
        int idx = base + i;
        if (idx < Nn) {
            int d = g_deg[idx] + 1;
            g_deg[idx] = 0;
            g_rowptr[idx] = run;
            g_pos[idx] = run;
            run += d;
        }
    }
    if (t == 1023) g_rowptr[Nn] = run;
}

__global__ void k_fill(const int* __restrict__ ei) {
    int t = blockIdx.x * blockDim.x + threadIdx.x;
    if (t < Ee) {
        int s = ei[t], d = ei[Ee + t];
        int p = atomicAdd(&g_pos[d], 1);
        g_esrc[p] = s;
    } else if (t < TOTE) {
        int n = t - Ee;
        int p = atomicAdd(&g_pos[n], 1);
        g_esrc[p] = n;
    }
}

// ---------------- fp16 tensor-core GEMM, 3-stage cp.async pipeline -------------
// C16[M,N] = A[M,K] @ Bt[N,K]^T. BM=BN=128, BK=32, 256 threads, 8 warps (2x4).
#define GBUF (128 * 40)  // halves per stage per operand
__global__ __launch_bounds__(256) void k_gemm_h(const __half* __restrict__ A,
                                                const __half* __restrict__ Bt,
                                                __half* __restrict__ C16, int M_,
                                                int K, int N) {
    extern __shared__ __align__(16) __half gs[];
    __half* As = gs;             // [3][128][40]
    __half* Bs = gs + 3 * GBUF;  // [3][128][40]
    int tid = threadIdx.x;
    int brow = blockIdx.y * 128, bcol = blockIdx.x * 128;
    int w = tid >> 5, lane = tid & 31;
    int wm = w & 1, wn = w >> 1;
    int g = lane >> 2, t4 = lane & 3;

    float acc[4][4][4];
#pragma unroll
    for (int mt = 0; mt < 4; mt++)
#pragma unroll
        for (int nt = 0; nt < 4; nt++)
#pragma unroll
            for (int p = 0; p < 4; p++) acc[mt][nt][p] = 0.f;

    int cr = tid >> 1;           // row 0..127
    int cc = (tid & 1) * 2;      // 16B-chunk col {0,2}
    bool avalid = (brow + cr) < M_;
    const __half* arow = A + (size_t)(avalid ? brow + cr : 0) * K + cc * 8;
    const __half* brw = Bt + (size_t)(bcol + cr) * K + cc * 8;
    unsigned sa = (unsigned)__cvta_generic_to_shared(As + cr * 40 + cc * 8);
    unsigned sbx = (unsigned)__cvta_generic_to_shared(Bs + cr * 40 + cc * 8);

    auto ISSUE = [&](int kt, int s) {
        unsigned soff = (unsigned)(s * GBUF * 2);
        const __half* ap = arow + kt * 32;
        cp16(sa + soff, ap, avalid);
        cp16(sa + soff + 16, ap + 8, avalid);
        const __half* bp = brw + kt * 32;
        cp16(sbx + soff, bp, true);
        cp16(sbx + soff + 16, bp + 8, true);
        asm volatile("cp.async.commit_group;");
    };

    int KT = K >> 5;
    ISSUE(0, 0);
    if (KT > 1)
        ISSUE(1, 1);
    else
        asm volatile("cp.async.commit_group;");

    for (int kt = 0; kt < KT; kt++) {
        asm volatile("cp.async.wait_group 1;");
        __syncthreads();
        if (kt + 2 < KT)
            ISSUE(kt + 2, (kt + 2) % 3);
        else
            asm volatile("cp.async.commit_group;");

        const __half* Ab = As + (kt % 3) * GBUF;
        const __half* Bb = Bs + (kt % 3) * GBUF;
#pragma unroll
        for (int ks = 0; ks < 2; ks++) {
            int kb = ks * 16 + 2 * t4;
            unsigned af[4][4], bfr[4][2];
#pragma unroll
            for (int mt = 0; mt < 4; mt++) {
                int r0 = wm * 64 + mt * 16 + g;
                af[mt][0] = *(const unsigned*)&Ab[r0 * 40 + kb];
                af[mt][1] = *(const unsigned*)&Ab[(r0 + 8) * 40 + kb];
                af[mt][2] = *(const unsigned*)&Ab[r0 * 40 + kb + 8];
                af[mt][3] = *(const unsigned*)&Ab[(r0 + 8) * 40 + kb + 8];
            }
#pragma unroll
            for (int nt = 0; nt < 4; nt++) {
                int n0 = wn * 32 + nt * 8 + g;
                bfr[nt][0] = *(const unsigned*)&Bb[n0 * 40 + kb];
                bfr[nt][1] = *(const unsigned*)&Bb[n0 * 40 + kb + 8];
            }
#pragma unroll
            for (int mt = 0; mt < 4; mt++)
#pragma unroll
                for (int nt = 0; nt < 4; nt++) mma16816(acc[mt][nt], af[mt], bfr[nt]);
        }
    }

#pragma unroll
    for (int mt = 0; mt < 4; mt++) {
        int r0 = brow + wm * 64 + mt * 16 + g;
#pragma unroll
        for (int nt = 0; nt < 4; nt++) {
            int c0 = bcol + wn * 32 + nt * 8 + 2 * t4;
            if (r0 < M_)
                *(__half2*)(C16 + (size_t)r0 * N + c0) =
                    __floats2half2_rn(acc[mt][nt][0], acc[mt][nt][1]);
            if (r0 + 8 < M_)
                *(__half2*)(C16 + (size_t)(r0 + 8) * N + c0) =
                    __floats2half2_rn(acc[mt][nt][2], acc[mt][nt][3]);
        }
    }
}
#define GEMM_SMEM (6 * GBUF * 2)  // 61440 bytes

// ---------------- per-node attention coefficients (fp16 h) --------------------
__global__ void k_coef(const __half* __restrict__ hbuf, const float* __restrict__ asrc,
                       const float* __restrict__ adst, int H, int D) {
    int idx = blockIdx.x * blockDim.x + threadIdx.x;
    if (idx >= Nn * H) return;
    int n = idx / H, h = idx % H;
    const uint4* hp = (const uint4*)(hbuf + (size_t)n * H * D + h * D);
    const float4* as = (const float4*)(asrc + h * D);
    const float4* ad = (const float4*)(adst + h * D);
    float ss = 0.f, sd = 0.f;
    for (int j = 0; j < D / 8; j++) {
        uint4 hv = hp[j];
        float2 p0 = __half22float2(*(__half2*)&hv.x);
        float2 p1 = __half22float2(*(__half2*)&hv.y);
        float2 p2 = __half22float2(*(__half2*)&hv.z);
        float2 p3 = __half22float2(*(__half2*)&hv.w);
        float4 a0 = as[2 * j], a1 = as[2 * j + 1];
        float4 d0 = ad[2 * j], d1 = ad[2 * j + 1];
        ss += p0.x * a0.x + p0.y * a0.y + p1.x * a0.z + p1.y * a0.w + p2.x * a1.x +
              p2.y * a1.y + p3.x * a1.z + p3.y * a1.w;
        sd += p0.x * d0.x + p0.y * d0.y + p1.x * d0.z + p1.y * d0.w + p2.x * d1.x +
              p2.y * d1.y + p3.x * d1.z + p3.y * d1.w;
    }
    g_als[idx] = ss;
    g_ald[idx] = sd;
}

// ---------------- aggregation: no-max softmax, 4-edge unroll + esrc prefetch ---
// (round-9 form — best known; warp per node)
template <int H, int D, int ACT>
__global__ void k_aggr(const __half* __restrict__ h16, const float* __restrict__ bias,
                       __half* __restrict__ outh) {
    constexpr int HD = H * D;
    constexpr int F = HD / 32;  // 8 or 4
    int lane = threadIdx.x & 31;
    int n = (blockIdx.x * blockDim.x + threadIdx.x) >> 5;
    if (n >= Nn) return;
    int beg = g_rowptr[n], end = g_rowptr[n + 1];
    const int fb = lane * F;
    const int myh = fb / D;
    const float am = g_ald[n * H + myh];

    float den = 0.f;
    float acc[F];
#pragma unroll
    for (int j = 0; j < F; j++) acc[j] = 0.f;

    auto GATHER = [&](int s, float* hf) {
        if constexpr (F == 8) {
            uint4 hv = *(const uint4*)(h16 + (size_t)s * HD + fb);
            float2 p0 = __half22float2(*(__half2*)&hv.x);
            float2 p1 = __half22float2(*(__half2*)&hv.y);
            float2 p2 = __half22float2(*(__half2*)&hv.z);
            float2 p3 = __half22float2(*(__half2*)&hv.w);
            hf[0] = p0.x; hf[1] = p0.y; hf[2] = p1.x; hf[3] = p1.y;
            hf[4] = p2.x; hf[5] = p2.y; hf[6] = p3.x; hf[7] = p3.y;
        } else {
            uint2 hv = *(const uint2*)(h16 + (size_t)s * HD + fb);
            float2 p0 = __half22float2(*(__half2*)&hv.x);
            float2 p1 = __half22float2(*(__half2*)&hv.y);
            hf[0] = p0.x; hf[1] = p0.y; hf[2] = p1.x; hf[3] = p1.y;
        }
    };
    auto ONE = [&](int s0) {
        float l0 = g_als[s0 * H + myh] + am;
        l0 = l0 > 0.f ? l0 : 0.2f * l0;
        float ha[F];
        GATHER(s0, ha);
        float w0 = __expf(l0);
        den += w0;
#pragma unroll
        for (int j = 0; j < F; j++) acc[j] = fmaf(w0, ha[j], acc[j]);
    };

    int i = beg;
    int aligned = (beg + 3) & ~3;
    if (aligned > end) aligned = end;
    for (; i < aligned; i++) ONE(g_esrc[i]);

    if (i + 3 < end) {
        int4 s4 = *(const int4*)(g_esrc + i);
        for (; i + 3 < end; i += 4) {
            int4 s4n = (i + 7 < end) ? *(const int4*)(g_esrc + i + 4) : s4;
            float l0 = g_als[s4.x * H + myh] + am;
            float l1 = g_als[s4.y * H + myh] + am;
            float l2 = g_als[s4.z * H + myh] + am;
            float l3 = g_als[s4.w * H + myh] + am;
            float ha[F], hb[F], hc[F], hd[F];
            GATHER(s4.x, ha);
            GATHER(s4.y, hb);
            GATHER(s4.z, hc);
            GATHER(s4.w, hd);
            l0 = l0 > 0.f ? l0 : 0.2f * l0;
            l1 = l1 > 0.f ? l1 : 0.2f * l1;
            l2 = l2 > 0.f ? l2 : 0.2f * l2;
            l3 = l3 > 0.f ? l3 : 0.2f * l3;
            float w0 = __expf(l0), w1 = __expf(l1);
            float w2 = __expf(l2), w3 = __expf(l3);
            den += (w0 + w1) + (w2 + w3);
#pragma unroll
            for (int j = 0; j < F; j++) {
                float t0 = fmaf(w0, ha[j], w1 * hb[j]);
                float t1 = fmaf(w2, hc[j], w3 * hd[j]);
                acc[j] += t0 + t1;
            }
            s4 = s4n;
        }
    }
    for (; i < end; i++) ONE(g_esrc[i]);

    float inv = 1.f / (den + 1e-16f);
    float o[F];
#pragma unroll
    for (int j = 0; j < F; j++) {
        float v = acc[j] * inv + bias[fb + j];
        if (ACT) v = v > 0.f ? v : (__expf(v) - 1.f);
        o[j] = v;
    }
    if constexpr (F == 8) {
        __half2 q0 = __floats2half2_rn(o[0], o[1]);
        __half2 q1 = __floats2half2_rn(o[2], o[3]);
        __half2 q2 = __floats2half2_rn(o[4], o[5]);
        __half2 q3 = __floats2half2_rn(o[6], o[7]);
        uint4 hv;
        hv.x = *(unsigned*)&q0;
        hv.y = *(unsigned*)&q1;
        hv.z = *(unsigned*)&q2;
        hv.w = *(unsigned*)&q3;
        *(uint4*)(outh + (size_t)n * HD + fb) = hv;
    } else {
        __half2 q0 = __floats2half2_rn(o[0], o[1]);
        __half2 q1 = __floats2half2_rn(o[2], o[3]);
        uint2 hv;
        hv.x = *(unsigned*)&q0;
        hv.y = *(unsigned*)&q1;
        *(uint2*)(outh + (size_t)n * HD + fb) = hv;
    }
}

// ---------------- decoder: tensor-core GEMM, 256 edges x 64 outs per block -----
#define DEC_M 256
__global__ __launch_bounds__(256) void k_decode3(const __half* __restrict__ z16,
                                                 const int* __restrict__ eli,
                                                 const float* __restrict__ x,
                                                 const __half* __restrict__ Wl1t,
                                                 const float* __restrict__ bl1,
                                                 const float* __restrict__ Wl2,
                                                 const float* __restrict__ bl2,
                                                 const float* __restrict__ tb,
                                                 float* __restrict__ out) {
    extern __shared__ __align__(16) __half ds[];
    __half* Asm = ds;                    // [256][264]
    __half* Wsm = ds + 256 * 264;        // [64][264]
    int* sls = (int*)(Wsm + 64 * 264);
    int* sld = sls + DEC_M;

    int tid = threadIdx.x;
    int e0 = blockIdx.x * DEC_M;

    for (int i = tid; i < DEC_M; i += 256) {
        int e = e0 + i;
        sls[i] = (e < ELn) ? eli[e] : 0;
        sld[i] = (e < ELn) ? eli[ELn + e] : 0;
    }
    for (int i = tid; i < 64 * 32; i += 256) {
        int nr = i >> 5, kc = (i & 31) * 8;
        *(uint4*)&Wsm[nr * 264 + kc] = *(const uint4*)&Wl1t[nr * 256 + kc];
    }
    __syncthreads();

    for (int i = tid; i < DEC_M * 32; i += 256) {
        int e = i >> 5, off = i & 31;
        int node = (off < 16) ? sls[e] : sld[e];
        int kc = (off & 15) * 8;
        *(uint4*)&Asm[e * 264 + (off < 16 ? 0 : 128) + kc] =
            *(const uint4*)&z16[(size_t)node * 128 + kc];
    }
    __syncthreads();

    int w = tid >> 5, lane = tid & 31;
    int g = lane >> 2, t4 = lane & 3;

    float acc[2][8][4];
#pragma unroll
    for (int mt = 0; mt < 2; mt++)
#pragma unroll
        for (int nt = 0; nt < 8; nt++)
#pragma unroll
            for (int p = 0; p < 4; p++) acc[mt][nt][p] = 0.f;

#pragma unroll 4
    for (int ks = 0; ks < 16; ks++) {
        int kb = ks * 16 + 2 * t4;
        unsigned af[2][4];
#pragma unroll
        for (int mt = 0; mt < 2; mt++) {
            int r0 = w * 32 + mt * 16 + g;
            af[mt][0] = *(const unsigned*)&Asm[r0 * 264 + kb];
            af[mt][1] = *(const unsigned*)&Asm[(r0 + 8) * 264 + kb];
            af[mt][2] = *(const unsigned*)&Asm[r0 * 264 + kb + 8];
            af[mt][3] = *(const unsigned*)&Asm[(r0 + 8) * 264 + kb + 8];
        }
#pragma unroll
        for (int nt = 0; nt < 8; nt++) {
            int n0 = nt * 8 + g;
            unsigned bfr[2];
            bfr[0] = *(const unsigned*)&Wsm[n0 * 264 + kb];
            bfr[1] = *(const unsigned*)&Wsm[n0 * 264 + kb + 8];
            mma16816(acc[0][nt], af[0], bfr);
            mma16816(acc[1][nt], af[1], bfr);
        }
    }

    float b1v[16], w2v[16];
#pragma unroll
    for (int nt = 0; nt < 8; nt++) {
        int c0 = nt * 8 + 2 * t4;
        b1v[2 * nt] = bl1[c0];
        b1v[2 * nt + 1] = bl1[c0 + 1];
        w2v[2 * nt] = Wl2[c0];
        w2v[2 * nt + 1] = Wl2[c0 + 1];
    }
    float b2 = bl2[0];

#pragma unroll
    for (int mt = 0; mt < 2; mt++) {
        float p0 = 0.f, p1 = 0.f;
#pragma unroll
        for (int nt = 0; nt < 8; nt++) {
            float h00 = fmaxf(acc[mt][nt][0] + b1v[2 * nt], 0.f);
            float h01 = fmaxf(acc[mt][nt][1] + b1v[2 * nt + 1], 0.f);
            p0 = fmaf(h00, w2v[2 * nt], p0);
            p0 = fmaf(h01, w2v[2 * nt + 1], p0);
            float h10 = fmaxf(acc[mt][nt][2] + b1v[2 * nt], 0.f);
            float h11 = fmaxf(acc[mt][nt][3] + b1v[2 * nt + 1], 0.f);
            p1 = fmaf(h10, w2v[2 * nt], p1);
            p1 = fmaf(h11, w2v[2 * nt + 1], p1);
        }
        p0 += __shfl_xor_sync(0xffffffffu, p0, 1);
        p0 += __shfl_xor_sync(0xffffffffu, p0, 2);
        p1 += __shfl_xor_sync(0xffffffffu, p1, 1);
        p1 += __shfl_xor_sync(0xffffffffu, p1, 2);
        if (t4 == 0) {
            int r = w * 32 + mt * 16 + g;
            int e = e0 + r;
            if (e < ELn) {
                int tls = (int)x[(size_t)sls[r] * 33];
                int tld = (int)x[(size_t)sld[r] * 33];
                out[e] = p0 + b2 + tb[tls * NTY + tld];
            }
            e = e0 + r + 8;
            if (e < ELn) {
                int tls = (int)x[(size_t)sls[r + 8] * 33];
                int tld = (int)x[(size_t)sld[r + 8] * 33];
                out[e] = p1 + b2 + tb[tls * NTY + tld];
            }
        }
    }
}

// ---------------- launch -------------
extern "C" void kernel_launch(void* const* d_in, const int* in_sizes, int n_in,
                              void* d_out, int out_size) {
    const float* x = (const float*)d_in[0];
    const int* ei = (const int*)d_in[1];
    const int* eli = (const int*)d_in[2];
    const float* emb = (const float*)d_in[3];
    const float* W1 = (const float*)d_in[4];
    const float* as1 = (const float*)d_in[5];
    const float* ad1 = (const float*)d_in[6];
    const float* b1 = (const float*)d_in[7];
    const float* W2 = (const float*)d_in[8];
    const float* as2 = (const float*)d_in[9];
    const float* ad2 = (const float*)d_in[10];
    const float* b2 = (const float*)d_in[11];
    const float* W3 = (const float*)d_in[12];
    const float* as3 = (const float*)d_in[13];
    const float* ad3 = (const float*)d_in[14];
    const float* b3 = (const float*)d_in[15];
    const float* Wl1 = (const float*)d_in[16];
    const float* bl1 = (const float*)d_in[17];
    const float* Wl2 = (const float*)d_in[18];
    const float* bl2 = (const float*)d_in[19];
    const float* tb = (const float*)d_in[20];
    float* out = (float*)d_out;

    __half *feat16, *h16, *za16, *zb16, *w1t, *w2t, *w3t, *wl1t;
    cudaGetSymbolAddress((void**)&feat16, g_feat16);
    cudaGetSymbolAddress((void**)&h16, g_h16);
    cudaGetSymbolAddress((void**)&za16, g_za16);
    cudaGetSymbolAddress((void**)&zb16, g_zb16);
    cudaGetSymbolAddress((void**)&w1t, g_w1t);
    cudaGetSymbolAddress((void**)&w2t, g_w2t);
    cudaGetSymbolAddress((void**)&w3t, g_w3t);
    cudaGetSymbolAddress((void**)&wl1t, g_wl1t);

    const int AGW = (Nn * 32 + 255) / 256;
    const int GY = (Nn + 127) / 128;

    cudaFuncSetAttribute(k_gemm_h, cudaFuncAttributeMaxDynamicSharedMemorySize, GEMM_SMEM);

    // Fork-join: CSR build runs concurrently with data prep + layer-1 GEMM + coef.
    cudaStream_t sb = 0;
    cudaEvent_t evFork = nullptr, evJoin = nullptr;
    bool forked = (cudaStreamCreateWithFlags(&sb, cudaStreamNonBlocking) == cudaSuccess) &&
                  (cudaEventCreateWithFlags(&evFork, cudaEventDisableTiming) == cudaSuccess) &&
                  (cudaEventCreateWithFlags(&evJoin, cudaEventDisableTiming) == cudaSuccess);

    if (forked) {
        cudaEventRecord(evFork, 0);
        cudaStreamWaitEvent(sb, evFork, 0);
        k_prep_graph<<<(Ee + 255) / 256, 256, 0, sb>>>(ei);
        k_scan<<<1, 1024, 0, sb>>>();
        k_fill<<<(TOTE + 255) / 256, 256, 0, sb>>>(ei);
        cudaEventRecord(evJoin, sb);
    } else {
        k_prep_graph<<<(Ee + 255) / 256, 256>>>(ei);
        k_scan<<<1, 1024>>>();
        k_fill<<<(TOTE + 255) / 256, 256>>>(ei);
    }

    // main stream: data prep + layer-1 GEMM + coef (independent of CSR)
    k_prep_data<<<(PREPD_TASKS + 255) / 256, 256>>>(x, emb, W1, W2, W3, Wl1);
    k_gemm_h<<<dim3(2, GY), 256, GEMM_SMEM>>>(feat16, w1t, h16, Nn, 64, 256);
    k_coef<<<(Nn * 4 + 255) / 256, 256>>>(h16, as1, ad1, 4, 64);

    if (forked) cudaStreamWaitEvent(0, evJoin, 0);

    // layer 1 aggregation (needs CSR + coef)
    k_aggr<4, 64, 1><<<AGW, 256>>>(h16, b1, za16);

    // layer 2
    k_gemm_h<<<dim3(2, GY), 256, GEMM_SMEM>>>(za16, w2t, h16, Nn, 256, 256);
    k_coef<<<(Nn * 2 + 255) / 256, 256>>>(h16, as2, ad2, 2, 128);
    k_aggr<2, 128, 1><<<AGW, 256>>>(h16, b2, zb16);

    // layer 3 (output fp16, 128 wide -> za16 reused)
    k_gemm_h<<<dim3(1, GY), 256, GEMM_SMEM>>>(zb16, w3t, h16, Nn, 256, 128);
    k_coef<<<(Nn * 1 + 255) / 256, 256>>>(h16, as3, ad3, 1, 128);
    k_aggr<1, 128, 0><<<AGW, 256>>>(h16, b3, za16);

    // decoder (tensor core)
    const int DSMEM = (256 * 264 + 64 * 264) * 2 + 2 * DEC_M * 4;  // ~171KB
    cudaFuncSetAttribute(k_decode3, cudaFuncAttributeMaxDynamicSharedMemorySize, DSMEM);
    k_decode3<<<(ELn + DEC_M - 1) / DEC_M, 256, DSMEM>>>(za16, eli, x, wl1t, bl1, Wl2, bl2,
                                                         tb, out);
}